// round 13
// baseline (speedup 1.0000x reference)
#include <cuda_runtime.h>
#include <cuda_fp16.h>
#include <mma.h>
#include <cstdint>

using namespace nvcuda;

#define NN 100000
#define EE 1600000
#define DD 128
#define SCAN_T 1024

// Scratch (__device__ globals). d_g padded 128 rows for full-tile wmma stores.
__device__ float  d_g[(size_t)(NN + 128) * DD];
__device__ float  d_dinv[NN];
__device__ int    d_deg[NN];
__device__ int    d_rowptr[NN + 1];
__device__ int    d_cursor[NN];
__device__ int    d_srcs[EE];      // edges grouped by target
__device__ int    d_tgts[EE];      // target per grouped position
__device__ __half d_WcTh[DD * DD]; // WcT[k][c], fp16

// ---------------------------------------------------------------------------
__global__ void zero_deg_kernel(int n) {
    int i = blockIdx.x * blockDim.x + threadIdx.x;
    if (i < n) d_deg[i] = 0;
}

// count in-degrees; 4 edges per thread
__global__ void count_deg_kernel(const int* __restrict__ ei, int E) {
    int t = blockIdx.x * blockDim.x + threadIdx.x;
    int e = t * 4;
    if (e + 4 <= E) {
        int4 c = __ldg((const int4*)&ei[E + e]);
        atomicAdd(&d_deg[c.x], 1);
        atomicAdd(&d_deg[c.y], 1);
        atomicAdd(&d_deg[c.z], 1);
        atomicAdd(&d_deg[c.w], 1);
    } else {
        for (; e < E; e++) atomicAdd(&d_deg[__ldg(&ei[E + e])], 1);
    }
}

// single-block scan: rowptr/cursor = exclusive scan(deg); dinv = rsqrt(deg+1)
__global__ __launch_bounds__(SCAN_T) void scan_kernel(int n) {
    __shared__ int ssum[SCAN_T];
    int t = threadIdx.x;
    int chunk = (n + SCAN_T - 1) / SCAN_T;
    int lo = t * chunk;
    int hi = min(lo + chunk, n);
    int s = 0;
    for (int i = lo; i < hi; i++) s += d_deg[i];
    ssum[t] = s;
    __syncthreads();
    for (int off = 1; off < SCAN_T; off <<= 1) {
        int tmp = (t >= off) ? ssum[t - off] : 0;
        __syncthreads();
        ssum[t] += tmp;
        __syncthreads();
    }
    int run = ssum[t] - s;
    for (int i = lo; i < hi; i++) {
        int d = d_deg[i];
        d_rowptr[i] = run;
        d_cursor[i] = run;
        d_dinv[i]   = rsqrtf((float)(d + 1));
        run += d;
    }
    if (t == SCAN_T - 1) d_rowptr[n] = ssum[SCAN_T - 1];
}

// group edges by target; 4 edges per thread
__global__ void fill_csr_kernel(const int* __restrict__ ei, int E) {
    int t = blockIdx.x * blockDim.x + threadIdx.x;
    int e = t * 4;
    if (e + 4 <= E) {
        int4 r = __ldg((const int4*)&ei[e]);
        int4 c = __ldg((const int4*)&ei[E + e]);
        int p;
        p = atomicAdd(&d_cursor[c.x], 1); d_srcs[p] = r.x; d_tgts[p] = c.x;
        p = atomicAdd(&d_cursor[c.y], 1); d_srcs[p] = r.y; d_tgts[p] = c.y;
        p = atomicAdd(&d_cursor[c.z], 1); d_srcs[p] = r.z; d_tgts[p] = c.z;
        p = atomicAdd(&d_cursor[c.w], 1); d_srcs[p] = r.w; d_tgts[p] = c.w;
    } else {
        for (; e < E; e++) {
            int r = __ldg(&ei[e]);
            int c = __ldg(&ei[E + e]);
            int p = atomicAdd(&d_cursor[c], 1);
            d_srcs[p] = r; d_tgts[p] = c;
        }
    }
}

// WcTh[k][c] = fp16(sum_m Wg[c][m]*Wl[m][k])
__global__ void combine_w_kernel(const float* __restrict__ Wl,
                                 const float* __restrict__ Wg) {
    int k = blockIdx.x;
    int c = threadIdx.x;
    float s0 = 0.f, s1 = 0.f, s2 = 0.f, s3 = 0.f;
#pragma unroll 8
    for (int m = 0; m < DD; m += 4) {
        s0 += __ldg(&Wg[c * DD + m + 0]) * __ldg(&Wl[(m + 0) * DD + k]);
        s1 += __ldg(&Wg[c * DD + m + 1]) * __ldg(&Wl[(m + 1) * DD + k]);
        s2 += __ldg(&Wg[c * DD + m + 2]) * __ldg(&Wl[(m + 2) * DD + k]);
        s3 += __ldg(&Wg[c * DD + m + 3]) * __ldg(&Wl[(m + 3) * DD + k]);
    }
    d_WcTh[k * DD + c] = __float2half_rn((s0 + s1) + (s2 + s3));
}

// fp16 wmma GEMM + fused epilogue (R12-proven, 37 µs).
//   g[i][:]   = (dinv[i] * x[i]) @ WcT   (fp16 in, fp32 accum)
//   out[i][:] = dinv[i] * g[i] + b
#define XS_LD 136
#define SMEM_HALVES (2 * 128 * XS_LD)

__global__ __launch_bounds__(256, 2) void gemm_g_kernel(const float* __restrict__ x,
                                                        const float* __restrict__ bias,
                                                        float* __restrict__ out, int n) {
    extern __shared__ __half sm[];
    __half* xs = sm;
    __half* ws = sm + 128 * XS_LD;

    const int tid = threadIdx.x;
    const int row0 = blockIdx.x * 128;
    const int warp = tid >> 5;
    const int wrow = (warp >> 1) * 32;
    const int wcol = (warp & 1) * 64;

    const float4* x4 = (const float4*)x;
#pragma unroll
    for (int i = 0; i < 16; i++) {
        int idx = tid + 256 * i;
        int r = idx >> 5;
        int c4 = idx & 31;
        int grow = row0 + r;
        float4 v = make_float4(0.f, 0.f, 0.f, 0.f);
        float di = 0.f;
        if (grow < n) {
            di = d_dinv[grow];
            v = __ldg(&x4[grow * 32 + c4]);
        }
        __half2 h0 = __floats2half2_rn(v.x * di, v.y * di);
        __half2 h1 = __floats2half2_rn(v.z * di, v.w * di);
        uint2 p;
        p.x = *reinterpret_cast<unsigned*>(&h0);
        p.y = *reinterpret_cast<unsigned*>(&h1);
        *(uint2*)&xs[r * XS_LD + c4 * 4] = p;
    }
    const uint4* w16 = (const uint4*)d_WcTh;
#pragma unroll
    for (int i = 0; i < 8; i++) {
        int idx = tid + 256 * i;
        int k = idx >> 4;
        int c8 = idx & 15;
        uint4 v = __ldg(&w16[k * 16 + c8]);
        *(uint4*)&ws[k * XS_LD + c8 * 8] = v;
    }
    __syncthreads();

    wmma::fragment<wmma::accumulator, 16, 16, 16, float> acc[2][4];
#pragma unroll
    for (int i = 0; i < 2; i++)
#pragma unroll
        for (int j = 0; j < 4; j++) wmma::fill_fragment(acc[i][j], 0.0f);

#pragma unroll
    for (int ks = 0; ks < 8; ks++) {
        wmma::fragment<wmma::matrix_a, 16, 16, 16, __half, wmma::row_major> a[2];
        wmma::load_matrix_sync(a[0], &xs[wrow * XS_LD + ks * 16], XS_LD);
        wmma::load_matrix_sync(a[1], &xs[(wrow + 16) * XS_LD + ks * 16], XS_LD);
#pragma unroll
        for (int j = 0; j < 4; j++) {
            wmma::fragment<wmma::matrix_b, 16, 16, 16, __half, wmma::row_major> b;
            wmma::load_matrix_sync(b, &ws[(ks * 16) * XS_LD + wcol + j * 16], XS_LD);
            wmma::mma_sync(acc[0][j], a[0], b, acc[0][j]);
            wmma::mma_sync(acc[1][j], a[1], b, acc[1][j]);
        }
    }

#pragma unroll
    for (int i = 0; i < 2; i++)
#pragma unroll
        for (int j = 0; j < 4; j++) {
            wmma::store_matrix_sync(
                &d_g[(size_t)(row0 + wrow + i * 16) * DD + wcol + j * 16],
                acc[i][j], DD, wmma::mem_row_major);
        }
    __syncthreads();

    const float4* g4 = (const float4*)d_g;
    const float4* bias4 = (const float4*)bias;
    float4* o4 = (float4*)out;
#pragma unroll
    for (int i = 0; i < 16; i++) {
        int idx = tid + 256 * i;
        int r = row0 + (idx >> 5);
        if (r < n) {
            int c4 = idx & 31;
            float di = d_dinv[r];
            float4 g = g4[r * 32 + c4];
            float4 bb = __ldg(&bias4[c4]);
            float4 o;
            o.x = di * g.x + bb.x;
            o.y = di * g.y + bb.y;
            o.z = di * g.z + bb.z;
            o.w = di * g.w + bb.w;
            o4[r * 32 + c4] = o;
        }
    }
}

// Segmented scatter over target-grouped edges: 8 edges/warp, front-batched
// independent g-row loads, register merge of equal-target runs, one v4 RED
// per distinct target in the window.
#define EPW 8
__global__ void seg_scatter_kernel(float* __restrict__ out, int E) {
    int warp = (blockIdx.x * blockDim.x + threadIdx.x) >> 5;
    int lane = threadIdx.x & 31;
    int base = warp * EPW;
    if (base >= E) return;
    int cnt = min(EPW, E - base);

    const float4* g4 = (const float4*)d_g;
    float4* o4 = (float4*)out;

    int   tg[EPW];
    float4 v[EPW];
#pragma unroll
    for (int t = 0; t < EPW; t++) {
        if (t < cnt) {
            int r = __ldg(&d_srcs[base + t]);
            tg[t] = __ldg(&d_tgts[base + t]);
            v[t] = __ldg(&g4[r * 32 + lane]);
        }
    }

    auto emit = [&](int c, float4 acc) {
        float dc = __ldg(&d_dinv[c]);
        acc.x *= dc; acc.y *= dc; acc.z *= dc; acc.w *= dc;
        float4* addr = &o4[c * 32 + lane];
        asm volatile("red.global.add.v4.f32 [%0], {%1,%2,%3,%4};"
                     :: "l"(addr), "f"(acc.x), "f"(acc.y), "f"(acc.z), "f"(acc.w)
                     : "memory");
    };

    float4 acc = v[0];
    int cur = tg[0];
#pragma unroll
    for (int t = 1; t < EPW; t++) {
        if (t < cnt) {
            if (tg[t] == cur) {
                acc.x += v[t].x; acc.y += v[t].y; acc.z += v[t].z; acc.w += v[t].w;
            } else {
                emit(cur, acc);
                acc = v[t];
                cur = tg[t];
            }
        }
    }
    emit(cur, acc);
}

extern "C" void kernel_launch(void* const* d_in, const int* in_sizes, int n_in,
                              void* d_out, int out_size) {
    const float* x  = (const float*)d_in[0];
    const int*   ei = (const int*)d_in[1];     // int32 on device
    const float* Wl = (const float*)d_in[2];
    const float* Wg = (const float*)d_in[3];
    const float* b  = (const float*)d_in[4];
    float* out = (float*)d_out;

    int n = in_sizes[0] / DD;     // 100000
    int E = in_sizes[1] / 2;      // 1600000

    zero_deg_kernel<<<(n + 255) / 256, 256>>>(n);
    int qthreads = (E + 3) / 4;
    count_deg_kernel<<<(qthreads + 255) / 256, 256>>>(ei, E);
    scan_kernel<<<1, SCAN_T>>>(n);
    fill_csr_kernel<<<(qthreads + 255) / 256, 256>>>(ei, E);
    combine_w_kernel<<<DD, DD>>>(Wl, Wg);

    size_t smem_bytes = SMEM_HALVES * sizeof(__half);   // 69632
    cudaFuncSetAttribute(gemm_g_kernel, cudaFuncAttributeMaxDynamicSharedMemorySize,
                         (int)smem_bytes);
    gemm_g_kernel<<<(n + 127) / 128, 256, smem_bytes>>>(x, b, out, n);

    int warps = (E + EPW - 1) / EPW;
    int sblocks = (warps * 32 + 255) / 256;
    seg_scatter_kernel<<<sblocks, 256>>>(out, E);
}

// round 14
// speedup vs baseline: 1.9753x; 1.9753x over previous
#include <cuda_runtime.h>
#include <cuda_fp16.h>
#include <mma.h>
#include <cstdint>

using namespace nvcuda;

#define NN 100000
#define EE 1600000
#define DD 128

// Scratch (__device__ globals). d_gh padded 128 rows for full-tile epilogue.
__device__ __half d_gh[(size_t)(NN + 128) * DD];   // g in fp16 (scatter messages)
__device__ float  d_dinv[NN];
__device__ int    d_deg[NN];
__device__ __half d_WcTh[DD * DD];                 // WcT[k][c], fp16

// ---------------------------------------------------------------------------
// 1) deg = 1 (self loop)
__global__ void prep_kernel(int n) {
    int i = blockIdx.x * blockDim.x + threadIdx.x;
    if (i < n) d_deg[i] = 1;
}

// 2) count in-degrees; 4 edges per thread
__global__ void count_deg_kernel(const int* __restrict__ ei, int E) {
    int t = blockIdx.x * blockDim.x + threadIdx.x;
    int e = t * 4;
    if (e + 4 <= E) {
        int4 c = __ldg((const int4*)&ei[E + e]);
        atomicAdd(&d_deg[c.x], 1);
        atomicAdd(&d_deg[c.y], 1);
        atomicAdd(&d_deg[c.z], 1);
        atomicAdd(&d_deg[c.w], 1);
    } else {
        for (; e < E; e++) atomicAdd(&d_deg[__ldg(&ei[E + e])], 1);
    }
}

// 3) fused: dinv = rsqrt(deg)  +  WcTh[k][c] = fp16(sum_m Wg[c][m]*Wl[m][k])
__global__ void dinv_combine_kernel(const float* __restrict__ Wl,
                                    const float* __restrict__ Wg, int n) {
    if (blockIdx.x < DD) {
        int k = blockIdx.x;
        int c = threadIdx.x;
        float s0 = 0.f, s1 = 0.f, s2 = 0.f, s3 = 0.f;
#pragma unroll 8
        for (int m = 0; m < DD; m += 4) {
            s0 += __ldg(&Wg[c * DD + m + 0]) * __ldg(&Wl[(m + 0) * DD + k]);
            s1 += __ldg(&Wg[c * DD + m + 1]) * __ldg(&Wl[(m + 1) * DD + k]);
            s2 += __ldg(&Wg[c * DD + m + 2]) * __ldg(&Wl[(m + 2) * DD + k]);
            s3 += __ldg(&Wg[c * DD + m + 3]) * __ldg(&Wl[(m + 3) * DD + k]);
        }
        d_WcTh[k * DD + c] = __float2half_rn((s0 + s1) + (s2 + s3));
    } else {
        int i = (blockIdx.x - DD) * blockDim.x + threadIdx.x;
        if (i < n) d_dinv[i] = rsqrtf((float)d_deg[i]);
    }
}

// 4) fp16 wmma GEMM, smem-staged epilogue.
//    g = (dinv*x) @ WcT  (fp16 in, fp32 accum) -> stage in smem ->
//    d_gh = fp16(g);  out = dinv*g + b   (no fp32 g in global at all)
#define XS_LD 136                      // halves
#define STG_LD 132                     // floats
#define SMEM_BYTES (2 * 128 * XS_LD * 2)   // 69632 >= 128*STG_LD*4 = 67584

__global__ __launch_bounds__(256, 2) void gemm_g_kernel(const float* __restrict__ x,
                                                        const float* __restrict__ bias,
                                                        float* __restrict__ out, int n) {
    extern __shared__ char smraw[];
    __half* xs = (__half*)smraw;               // [128][XS_LD]
    __half* ws = xs + 128 * XS_LD;             // [128][XS_LD]
    float*  stage = (float*)smraw;             // [128][STG_LD] (reused after MMAs)

    const int tid = threadIdx.x;
    const int row0 = blockIdx.x * 128;
    const int warp = tid >> 5;
    const int wrow = (warp >> 1) * 32;
    const int wcol = (warp & 1) * 64;

    // Load A: fp16(dinv * x)
    const float4* x4 = (const float4*)x;
#pragma unroll
    for (int i = 0; i < 16; i++) {
        int idx = tid + 256 * i;
        int r = idx >> 5;
        int c4 = idx & 31;
        int grow = row0 + r;
        float4 v = make_float4(0.f, 0.f, 0.f, 0.f);
        float di = 0.f;
        if (grow < n) {
            di = d_dinv[grow];
            v = __ldg(&x4[grow * 32 + c4]);
        }
        __half2 h0 = __floats2half2_rn(v.x * di, v.y * di);
        __half2 h1 = __floats2half2_rn(v.z * di, v.w * di);
        uint2 p;
        p.x = *reinterpret_cast<unsigned*>(&h0);
        p.y = *reinterpret_cast<unsigned*>(&h1);
        *(uint2*)&xs[r * XS_LD + c4 * 4] = p;
    }
    // Load B: WcTh
    const uint4* w16 = (const uint4*)d_WcTh;
#pragma unroll
    for (int i = 0; i < 8; i++) {
        int idx = tid + 256 * i;
        int k = idx >> 4;
        int c8 = idx & 15;
        uint4 v = __ldg(&w16[k * 16 + c8]);
        *(uint4*)&ws[k * XS_LD + c8 * 8] = v;
    }
    __syncthreads();

    wmma::fragment<wmma::accumulator, 16, 16, 16, float> acc[2][4];
#pragma unroll
    for (int i = 0; i < 2; i++)
#pragma unroll
        for (int j = 0; j < 4; j++) wmma::fill_fragment(acc[i][j], 0.0f);

#pragma unroll
    for (int ks = 0; ks < 8; ks++) {
        wmma::fragment<wmma::matrix_a, 16, 16, 16, __half, wmma::row_major> a[2];
        wmma::load_matrix_sync(a[0], &xs[wrow * XS_LD + ks * 16], XS_LD);
        wmma::load_matrix_sync(a[1], &xs[(wrow + 16) * XS_LD + ks * 16], XS_LD);
#pragma unroll
        for (int j = 0; j < 4; j++) {
            wmma::fragment<wmma::matrix_b, 16, 16, 16, __half, wmma::row_major> b;
            wmma::load_matrix_sync(b, &ws[(ks * 16) * XS_LD + wcol + j * 16], XS_LD);
            wmma::mma_sync(acc[0][j], a[0], b, acc[0][j]);
            wmma::mma_sync(acc[1][j], a[1], b, acc[1][j]);
        }
    }
    __syncthreads();   // A/B smem dead; reuse as fp32 stage

#pragma unroll
    for (int i = 0; i < 2; i++)
#pragma unroll
        for (int j = 0; j < 4; j++) {
            wmma::store_matrix_sync(&stage[(wrow + i * 16) * STG_LD + wcol + j * 16],
                                    acc[i][j], STG_LD, wmma::mem_row_major);
        }
    __syncthreads();

    // Epilogue from stage: d_gh (fp16) + out = dinv*g + b
    const float4* bias4 = (const float4*)bias;
    float4* o4 = (float4*)out;
    uint2* gh2 = (uint2*)d_gh;
#pragma unroll
    for (int i = 0; i < 16; i++) {
        int idx = tid + 256 * i;           // 0..4095
        int r = idx >> 5;
        int c4 = idx & 31;
        int grow = row0 + r;
        if (grow < n) {
            float4 g = *(float4*)&stage[r * STG_LD + c4 * 4];
            __half2 h0 = __floats2half2_rn(g.x, g.y);
            __half2 h1 = __floats2half2_rn(g.z, g.w);
            uint2 p;
            p.x = *reinterpret_cast<unsigned*>(&h0);
            p.y = *reinterpret_cast<unsigned*>(&h1);
            gh2[grow * 32 + c4] = p;
            float di = d_dinv[grow];
            float4 bb = __ldg(&bias4[c4]);
            float4 o;
            o.x = di * g.x + bb.x;
            o.y = di * g.y + bb.y;
            o.z = di * g.z + bb.z;
            o.w = di * g.w + bb.w;
            o4[grow * 32 + c4] = o;
        }
    }
}

// 5) scatter: flat random edge order (max slice parallelism); fp16 message
//    reads, fp32 v4 atomic accumulation. EPW edges per warp.
#define EPW 8
__global__ void scatter_kernel(const int* __restrict__ ei,
                               float* __restrict__ out, int E) {
    int warp = (blockIdx.x * blockDim.x + threadIdx.x) >> 5;
    int lane = threadIdx.x & 31;
    const uint2* gh2 = (const uint2*)d_gh;
    float4* o4 = (float4*)out;
    int base = warp * EPW;

    auto do_edge = [&](int e) {
        int r = __ldg(&ei[e]);
        int c = __ldg(&ei[E + e]);
        float dc = __ldg(&d_dinv[c]);
        uint2 raw = __ldg(&gh2[r * 32 + lane]);
        __half2 h0 = *reinterpret_cast<__half2*>(&raw.x);
        __half2 h1 = *reinterpret_cast<__half2*>(&raw.y);
        float2 f0 = __half22float2(h0);
        float2 f1 = __half22float2(h1);
        float4 v;
        v.x = f0.x * dc; v.y = f0.y * dc; v.z = f1.x * dc; v.w = f1.y * dc;
        float4* addr = &o4[c * 32 + lane];
        asm volatile("red.global.add.v4.f32 [%0], {%1,%2,%3,%4};"
                     :: "l"(addr), "f"(v.x), "f"(v.y), "f"(v.z), "f"(v.w)
                     : "memory");
    };

    if (base + EPW <= E) {
#pragma unroll
        for (int t = 0; t < EPW; t++) do_edge(base + t);
    } else {
        for (int e = base; e < E; e++) do_edge(e);
    }
}

extern "C" void kernel_launch(void* const* d_in, const int* in_sizes, int n_in,
                              void* d_out, int out_size) {
    const float* x  = (const float*)d_in[0];
    const int*   ei = (const int*)d_in[1];     // int32 on device
    const float* Wl = (const float*)d_in[2];
    const float* Wg = (const float*)d_in[3];
    const float* b  = (const float*)d_in[4];
    float* out = (float*)d_out;

    int n = in_sizes[0] / DD;     // 100000
    int E = in_sizes[1] / 2;      // 1600000

    prep_kernel<<<(n + 255) / 256, 256>>>(n);
    int qthreads = (E + 3) / 4;
    count_deg_kernel<<<(qthreads + 255) / 256, 256>>>(ei, E);
    dinv_combine_kernel<<<DD + (n + 127) / 128, 128>>>(Wl, Wg, n);

    cudaFuncSetAttribute(gemm_g_kernel, cudaFuncAttributeMaxDynamicSharedMemorySize,
                         SMEM_BYTES);
    gemm_g_kernel<<<(n + 127) / 128, 256, SMEM_BYTES>>>(x, b, out, n);

    int warps = (E + EPW - 1) / EPW;
    int sblocks = (warps * 32 + 255) / 256;
    scatter_kernel<<<sblocks, 256>>>(ei, out, E);
}

// round 15
// speedup vs baseline: 2.0190x; 1.0221x over previous
#include <cuda_runtime.h>
#include <cuda_fp16.h>
#include <mma.h>
#include <cstdint>

using namespace nvcuda;

#define NN 100000
#define EE 1600000
#define DD 128

// Scratch (__device__ globals; zero-initialized at module load).
__device__ __half d_gh[(size_t)(NN + 128) * DD];   // g in fp16 (scatter messages)
__device__ float  d_dinv[NN];
__device__ int    d_deg[NN];                       // starts 0; reset to 0 each call
__device__ __half d_WcTh[DD * DD];                 // WcT[k][c], fp16

// ---------------------------------------------------------------------------
// 1) count in-degrees; 4 edges per thread (deg starts at 0 each call)
__global__ void count_deg_kernel(const int* __restrict__ ei, int E) {
    int t = blockIdx.x * blockDim.x + threadIdx.x;
    int e = t * 4;
    if (e + 4 <= E) {
        int4 c = __ldg((const int4*)&ei[E + e]);
        atomicAdd(&d_deg[c.x], 1);
        atomicAdd(&d_deg[c.y], 1);
        atomicAdd(&d_deg[c.z], 1);
        atomicAdd(&d_deg[c.w], 1);
    } else {
        for (; e < E; e++) atomicAdd(&d_deg[__ldg(&ei[E + e])], 1);
    }
}

// 2) fused: dinv = rsqrt(deg + 1) with deg reset to 0 (restores replay invariant)
//    + WcTh[k][c] = fp16(sum_m Wg[c][m]*Wl[m][k])
__global__ void dinv_combine_kernel(const float* __restrict__ Wl,
                                    const float* __restrict__ Wg, int n) {
    if (blockIdx.x < DD) {
        int k = blockIdx.x;
        int c = threadIdx.x;
        float s0 = 0.f, s1 = 0.f, s2 = 0.f, s3 = 0.f;
#pragma unroll 8
        for (int m = 0; m < DD; m += 4) {
            s0 += __ldg(&Wg[c * DD + m + 0]) * __ldg(&Wl[(m + 0) * DD + k]);
            s1 += __ldg(&Wg[c * DD + m + 1]) * __ldg(&Wl[(m + 1) * DD + k]);
            s2 += __ldg(&Wg[c * DD + m + 2]) * __ldg(&Wl[(m + 2) * DD + k]);
            s3 += __ldg(&Wg[c * DD + m + 3]) * __ldg(&Wl[(m + 3) * DD + k]);
        }
        d_WcTh[k * DD + c] = __float2half_rn((s0 + s1) + (s2 + s3));
    } else {
        int i = (blockIdx.x - DD) * blockDim.x + threadIdx.x;
        if (i < n) {
            int d = d_deg[i];
            d_deg[i] = 0;                       // restore zero for next call
            d_dinv[i] = rsqrtf((float)(d + 1)); // +1 = self loop
        }
    }
}

// 3) fp16 wmma GEMM, smem-staged epilogue, grid-stride persistent CTAs.
//    g = (dinv*x) @ WcT  (fp16 in, fp32 accum) -> smem stage ->
//    d_gh = fp16(g);  out = dinv*g + b
#define XS_LD 136                          // halves
#define STG_LD 132                         // floats
#define SMEM_BYTES (2 * 128 * XS_LD * 2)   // 69632 >= 128*STG_LD*4 = 67584

__global__ __launch_bounds__(256, 2) void gemm_g_kernel(const float* __restrict__ x,
                                                        const float* __restrict__ bias,
                                                        float* __restrict__ out,
                                                        int n, int nblk) {
    extern __shared__ char smraw[];
    __half* xs = (__half*)smraw;               // [128][XS_LD]
    __half* ws = xs + 128 * XS_LD;             // [128][XS_LD]
    float*  stage = (float*)smraw;             // [128][STG_LD] (reused after MMAs)

    const int tid = threadIdx.x;
    const int warp = tid >> 5;
    const int wrow = (warp >> 1) * 32;
    const int wcol = (warp & 1) * 64;

    const float4* x4 = (const float4*)x;
    const uint4* w16 = (const uint4*)d_WcTh;
    const float4* bias4 = (const float4*)bias;
    float4* o4 = (float4*)out;
    uint2* gh2 = (uint2*)d_gh;

    for (int b0 = blockIdx.x; b0 < nblk; b0 += gridDim.x) {
        const int row0 = b0 * 128;

        // Load A: fp16(dinv * x)
#pragma unroll
        for (int i = 0; i < 16; i++) {
            int idx = tid + 256 * i;
            int r = idx >> 5;
            int c4 = idx & 31;
            int grow = row0 + r;
            float4 v = make_float4(0.f, 0.f, 0.f, 0.f);
            float di = 0.f;
            if (grow < n) {
                di = d_dinv[grow];
                v = __ldg(&x4[grow * 32 + c4]);
            }
            __half2 h0 = __floats2half2_rn(v.x * di, v.y * di);
            __half2 h1 = __floats2half2_rn(v.z * di, v.w * di);
            uint2 p;
            p.x = *reinterpret_cast<unsigned*>(&h0);
            p.y = *reinterpret_cast<unsigned*>(&h1);
            *(uint2*)&xs[r * XS_LD + c4 * 4] = p;
        }
        // Load B: WcTh
#pragma unroll
        for (int i = 0; i < 8; i++) {
            int idx = tid + 256 * i;
            int k = idx >> 4;
            int c8 = idx & 15;
            uint4 v = __ldg(&w16[k * 16 + c8]);
            *(uint4*)&ws[k * XS_LD + c8 * 8] = v;
        }
        __syncthreads();

        wmma::fragment<wmma::accumulator, 16, 16, 16, float> acc[2][4];
#pragma unroll
        for (int i = 0; i < 2; i++)
#pragma unroll
            for (int j = 0; j < 4; j++) wmma::fill_fragment(acc[i][j], 0.0f);

#pragma unroll
        for (int ks = 0; ks < 8; ks++) {
            wmma::fragment<wmma::matrix_a, 16, 16, 16, __half, wmma::row_major> a[2];
            wmma::load_matrix_sync(a[0], &xs[wrow * XS_LD + ks * 16], XS_LD);
            wmma::load_matrix_sync(a[1], &xs[(wrow + 16) * XS_LD + ks * 16], XS_LD);
#pragma unroll
            for (int j = 0; j < 4; j++) {
                wmma::fragment<wmma::matrix_b, 16, 16, 16, __half, wmma::row_major> b;
                wmma::load_matrix_sync(b, &ws[(ks * 16) * XS_LD + wcol + j * 16], XS_LD);
                wmma::mma_sync(acc[0][j], a[0], b, acc[0][j]);
                wmma::mma_sync(acc[1][j], a[1], b, acc[1][j]);
            }
        }
        __syncthreads();   // A/B smem dead; reuse as fp32 stage

#pragma unroll
        for (int i = 0; i < 2; i++)
#pragma unroll
            for (int j = 0; j < 4; j++) {
                wmma::store_matrix_sync(&stage[(wrow + i * 16) * STG_LD + wcol + j * 16],
                                        acc[i][j], STG_LD, wmma::mem_row_major);
            }
        __syncthreads();

        // Epilogue from stage: d_gh (fp16) + out = dinv*g + b
#pragma unroll
        for (int i = 0; i < 16; i++) {
            int idx = tid + 256 * i;           // 0..4095
            int r = idx >> 5;
            int c4 = idx & 31;
            int grow = row0 + r;
            if (grow < n) {
                float4 g = *(float4*)&stage[r * STG_LD + c4 * 4];
                __half2 h0 = __floats2half2_rn(g.x, g.y);
                __half2 h1 = __floats2half2_rn(g.z, g.w);
                uint2 p;
                p.x = *reinterpret_cast<unsigned*>(&h0);
                p.y = *reinterpret_cast<unsigned*>(&h1);
                gh2[grow * 32 + c4] = p;
                float di = d_dinv[grow];
                float4 bb = __ldg(&bias4[c4]);
                float4 o;
                o.x = di * g.x + bb.x;
                o.y = di * g.y + bb.y;
                o.z = di * g.z + bb.z;
                o.w = di * g.w + bb.w;
                o4[grow * 32 + c4] = o;
            }
        }
        __syncthreads();   // stage reads done before next iteration overwrites xs
    }
}

// 4) scatter: flat random edge order; fp16 message reads, fp32 v4 atomic adds.
#define EPW 8
__global__ void scatter_kernel(const int* __restrict__ ei,
                               float* __restrict__ out, int E) {
    int warp = (blockIdx.x * blockDim.x + threadIdx.x) >> 5;
    int lane = threadIdx.x & 31;
    const uint2* gh2 = (const uint2*)d_gh;
    float4* o4 = (float4*)out;
    int base = warp * EPW;

    auto do_edge = [&](int e) {
        int r = __ldg(&ei[e]);
        int c = __ldg(&ei[E + e]);
        float dc = __ldg(&d_dinv[c]);
        uint2 raw = __ldg(&gh2[r * 32 + lane]);
        __half2 h0 = *reinterpret_cast<__half2*>(&raw.x);
        __half2 h1 = *reinterpret_cast<__half2*>(&raw.y);
        float2 f0 = __half22float2(h0);
        float2 f1 = __half22float2(h1);
        float4 v;
        v.x = f0.x * dc; v.y = f0.y * dc; v.z = f1.x * dc; v.w = f1.y * dc;
        float4* addr = &o4[c * 32 + lane];
        asm volatile("red.global.add.v4.f32 [%0], {%1,%2,%3,%4};"
                     :: "l"(addr), "f"(v.x), "f"(v.y), "f"(v.z), "f"(v.w)
                     : "memory");
    };

    if (base + EPW <= E) {
#pragma unroll
        for (int t = 0; t < EPW; t++) do_edge(base + t);
    } else {
        for (int e = base; e < E; e++) do_edge(e);
    }
}

extern "C" void kernel_launch(void* const* d_in, const int* in_sizes, int n_in,
                              void* d_out, int out_size) {
    const float* x  = (const float*)d_in[0];
    const int*   ei = (const int*)d_in[1];     // int32 on device
    const float* Wl = (const float*)d_in[2];
    const float* Wg = (const float*)d_in[3];
    const float* b  = (const float*)d_in[4];
    float* out = (float*)d_out;

    int n = in_sizes[0] / DD;     // 100000
    int E = in_sizes[1] / 2;      // 1600000

    int qthreads = (E + 3) / 4;
    count_deg_kernel<<<(qthreads + 255) / 256, 256>>>(ei, E);
    dinv_combine_kernel<<<DD + (n + 127) / 128, 128>>>(Wl, Wg, n);

    int nblk = (n + 127) / 128;
    int gblocks = nblk < 296 ? nblk : 296;    // 2 CTAs/SM * 148 SMs
    cudaFuncSetAttribute(gemm_g_kernel, cudaFuncAttributeMaxDynamicSharedMemorySize,
                         SMEM_BYTES);
    gemm_g_kernel<<<gblocks, 256, SMEM_BYTES>>>(x, b, out, n, nblk);

    int warps = (E + EPW - 1) / EPW;
    int sblocks = (warps * 32 + 255) / 256;
    scatter_kernel<<<sblocks, 256>>>(ei, out, E);
}